// round 2
// baseline (speedup 1.0000x reference)
#include <cuda_runtime.h>
#include <cuda_bf16.h>
#include <stdint.h>

// ---------------------------------------------------------------------------
// LightGCN: N=100000 nodes, D=64, E=1000000 edges, 3 layers.
// out[0 : N*D]      = E0 (passthrough)
// out[N*D : 2*N*D]  = (E0 + x1 + x2 + x3) / 4,  x_{l+1} = scatter(norm * x_l[src] -> dst)
//
// edge_index dtype is detected at runtime (JAX int64 usually lowers to int32).
// Strategy: build CSR by destination each launch (graph-captured), then each
// layer is an atomic-free gather-reduce. x (25.6MB) is L2-resident.
// ---------------------------------------------------------------------------

#define MAXN 100000
#define MAXE 1000000
#define D    64

// Scratch (static __device__ globals -- no allocation allowed)
__device__ int   g_is64;
__device__ int   g_idx[2 * MAXE];     // normalized int32 edge_index [src | dst]
__device__ int   g_deg[MAXN];
__device__ float g_dinv[MAXN];
__device__ int   g_off[MAXN + 1];
__device__ int   g_cursor[MAXN];
__device__ int   g_blocksums[128];
__device__ int   g_src[MAXE];
__device__ float g_norm[MAXE];
__device__ float g_xA[MAXN * D];
__device__ float g_xB[MAXN * D];
__device__ float g_acc[MAXN * D];

// ---------------------------------------------------------------------------
// Dtype detection: if the buffer is int64 (values < 2^31), every odd 32-bit
// word is 0. For int32 random indices in [0,100000), 128 consecutive zeros
// at odd positions is impossible in practice.
__global__ void k_detect(const int* __restrict__ p) {
    if (threadIdx.x == 0 && blockIdx.x == 0) {
        int nz = 0;
        for (int i = 1; i < 256; i += 2) nz += (p[i] != 0);
        g_is64 = (nz == 0) ? 1 : 0;
    }
}

// Normalize edge_index to int32 in g_idx, and zero g_deg.
__global__ void k_extract(const void* __restrict__ ei, int E2, int N) {
    int i = blockIdx.x * blockDim.x + threadIdx.x;
    if (i < E2) {
        int v;
        if (g_is64) v = (int)((const long long*)ei)[i];
        else        v = ((const int*)ei)[i];
        g_idx[i] = v;
    }
    if (i < N) g_deg[i] = 0;
}

__global__ void k_histogram(int E) {
    int e = blockIdx.x * blockDim.x + threadIdx.x;
    if (e < E) {
        atomicAdd(&g_deg[g_idx[E + e]], 1);
    }
}

__global__ void k_dinv(int N) {
    int i = blockIdx.x * blockDim.x + threadIdx.x;
    if (i < N) {
        int d = g_deg[i];
        g_dinv[i] = (d > 0) ? rsqrtf((float)d) : 0.0f;
    }
}

// Block-local exclusive scan of g_deg into g_off; block totals to g_blocksums.
__global__ void k_scan_local(int N) {
    __shared__ int sh[1024];
    int tid = threadIdx.x;
    int i = blockIdx.x * 1024 + tid;
    int v = (i < N) ? g_deg[i] : 0;
    sh[tid] = v;
    __syncthreads();
    #pragma unroll
    for (int ofs = 1; ofs < 1024; ofs <<= 1) {
        int t = (tid >= ofs) ? sh[tid - ofs] : 0;
        __syncthreads();
        sh[tid] += t;
        __syncthreads();
    }
    if (i < N) g_off[i] = sh[tid] - v;  // exclusive within block
    if (tid == 1023) g_blocksums[blockIdx.x] = sh[1023];
}

__global__ void k_scan_blocks(int nb) {
    if (blockIdx.x == 0 && threadIdx.x == 0) {
        int run = 0;
        for (int b = 0; b < nb; b++) {
            int v = g_blocksums[b];
            g_blocksums[b] = run;
            run += v;
        }
    }
}

__global__ void k_scan_add(int N, int E) {
    int i = blockIdx.x * 1024 + threadIdx.x;
    if (i < N) {
        int v = g_off[i] + g_blocksums[blockIdx.x];
        g_off[i] = v;
        g_cursor[i] = v;
    }
    if (i == 0) g_off[N] = E;
}

__global__ void k_fill_csr(int E) {
    int e = blockIdx.x * blockDim.x + threadIdx.x;
    if (e < E) {
        int s = g_idx[e];
        int d = g_idx[E + e];
        int pos = atomicAdd(&g_cursor[d], 1);
        g_src[pos] = s;
        g_norm[pos] = g_dinv[s] * g_dinv[d];
    }
}

__global__ void k_init_acc(const float* __restrict__ E0, int ND) {
    int i = blockIdx.x * blockDim.x + threadIdx.x;
    if (i < ND) g_acc[i] = E0[i];
}

// One node per 64 threads (threadIdx.x = feature dim), 4 nodes per block.
// Warp lanes share the same csr_src/csr_norm address (HW broadcast); the
// x[src*64+d] gather is a contiguous 128B line per warp.
__global__ void k_propagate(const float* __restrict__ x, float* __restrict__ xn, int N) {
    int node = blockIdx.x * 4 + threadIdx.y;
    if (node >= N) return;
    int d = threadIdx.x;  // 0..63
    int beg = g_off[node];
    int end = g_off[node + 1];
    float s0 = 0.0f, s1 = 0.0f;
    int e = beg;
    for (; e + 1 < end; e += 2) {
        int sa = g_src[e];
        int sb = g_src[e + 1];
        float na = g_norm[e];
        float nb = g_norm[e + 1];
        s0 += na * x[(size_t)sa * D + d];
        s1 += nb * x[(size_t)sb * D + d];
    }
    if (e < end) {
        s0 += g_norm[e] * x[(size_t)g_src[e] * D + d];
    }
    float s = s0 + s1;
    size_t o = (size_t)node * D + d;
    xn[o] = s;
    g_acc[o] += s;
}

__global__ void k_final(const float* __restrict__ E0, float* __restrict__ out, int ND) {
    int i = blockIdx.x * blockDim.x + threadIdx.x;
    if (i < ND) {
        out[i] = E0[i];
        out[ND + i] = g_acc[i] * 0.25f;
    }
}

// ---------------------------------------------------------------------------

extern "C" void kernel_launch(void* const* d_in, const int* in_sizes, int n_in,
                              void* d_out, int out_size) {
    const float* E0 = (const float*)d_in[0];
    const void*  ei = d_in[1];
    float*       out = (float*)d_out;

    int N  = in_sizes[0] / D;   // 100000
    int E  = in_sizes[1] / 2;   // 1000000
    int ND = N * D;
    int E2 = 2 * E;

    void *pA = nullptr, *pB = nullptr;
    cudaGetSymbolAddress(&pA, g_xA);
    cudaGetSymbolAddress(&pB, g_xB);
    float* xA = (float*)pA;
    float* xB = (float*)pB;

    const int T = 256;
    int nb_scan = (N + 1023) / 1024;

    // Detect dtype + normalize indices (also zeros g_deg)
    k_detect<<<1, 32>>>((const int*)ei);
    k_extract<<<(E2 + T - 1) / T, T>>>(ei, E2, N);

    // Degree + normalization
    k_histogram<<<(E + T - 1) / T, T>>>(E);
    k_dinv<<<(N + T - 1) / T, T>>>(N);

    // CSR offsets (exclusive scan of deg)
    k_scan_local<<<nb_scan, 1024>>>(N);
    k_scan_blocks<<<1, 32>>>(nb_scan);
    k_scan_add<<<nb_scan, 1024>>>(N, E);

    // CSR fill (src index + edge norm)
    k_fill_csr<<<(E + T - 1) / T, T>>>(E);

    // acc = E0
    k_init_acc<<<(ND + T - 1) / T, T>>>(E0, ND);

    // 3 propagation layers (ping-pong), acc += x each layer
    dim3 pb(64, 4);
    int  pg = (N + 3) / 4;
    k_propagate<<<pg, pb>>>(E0, xA, N);
    k_propagate<<<pg, pb>>>(xA, xB, N);
    k_propagate<<<pg, pb>>>(xB, xA, N);

    // out = [E0, acc/4]
    k_final<<<(ND + T - 1) / T, T>>>(E0, out, ND);
}

// round 3
// speedup vs baseline: 1.7967x; 1.7967x over previous
#include <cuda_runtime.h>
#include <cuda_bf16.h>
#include <stdint.h>

// ---------------------------------------------------------------------------
// LightGCN: N=100000, D=64, E=1000000, 3 layers.
// out[0:ND] = E0 ; out[ND:2ND] = (E0 + x1 + x2 + x3)/4
//
// Algebra: with y = dinv (.) x,  x_l[dst] = dinv[dst] * sum_{src->dst} y_{l-1}[src]
//          y_l[dst] = dinv[dst]^2 * sum y_{l-1}[src]
// => inner loop is a pure gather-sum; no per-edge norm array needed.
// x is never materialized; only y ping-pongs + acc accumulates.
// ---------------------------------------------------------------------------

#define MAXN 100000
#define MAXE 1000000
#define D    64
#define DQ   16   // D/4 float4 per row

__device__ int    g_is64;
__device__ int    g_idx[2 * MAXE];
__device__ int    g_deg[MAXN];
__device__ float  g_dinv[MAXN];
__device__ int    g_off[MAXN + 1];
__device__ int    g_cursor[MAXN];
__device__ int    g_blocksums[128];
__device__ int    g_src[MAXE];
__device__ float4 g_yA[MAXN * DQ];
__device__ float4 g_yB[MAXN * DQ];
__device__ float4 g_acc[MAXN * DQ];

// ---------------------------------------------------------------------------
// int64 detection: int64 values < 2^31 have every odd 32-bit word == 0.
__global__ void k_detect(const int* __restrict__ p) {
    if (threadIdx.x == 0 && blockIdx.x == 0) {
        int nz = 0;
        for (int i = 1; i < 256; i += 2) nz += (p[i] != 0);
        g_is64 = (nz == 0) ? 1 : 0;
    }
}

__global__ void k_zero_deg(int N) {
    int i = blockIdx.x * blockDim.x + threadIdx.x;
    if (i < N) g_deg[i] = 0;
}

// Normalize indices to int32 AND histogram destinations in the same pass.
__global__ void k_extract_hist(const void* __restrict__ ei, int E) {
    int i = blockIdx.x * blockDim.x + threadIdx.x;
    int E2 = 2 * E;
    if (i < E2) {
        int v;
        if (g_is64) v = (int)((const long long*)ei)[i];
        else        v = ((const int*)ei)[i];
        g_idx[i] = v;
        if (i >= E) atomicAdd(&g_deg[v], 1);
    }
}

// Block-local exclusive scan of deg -> g_off (+ fused dinv computation).
__global__ void k_scan_local(int N) {
    __shared__ int sh[1024];
    int tid = threadIdx.x;
    int i = blockIdx.x * 1024 + tid;
    int v = (i < N) ? g_deg[i] : 0;
    if (i < N) g_dinv[i] = (v > 0) ? rsqrtf((float)v) : 0.0f;
    sh[tid] = v;
    __syncthreads();
    #pragma unroll
    for (int ofs = 1; ofs < 1024; ofs <<= 1) {
        int t = (tid >= ofs) ? sh[tid - ofs] : 0;
        __syncthreads();
        sh[tid] += t;
        __syncthreads();
    }
    if (i < N) g_off[i] = sh[tid] - v;
    if (tid == 1023) g_blocksums[blockIdx.x] = sh[1023];
}

__global__ void k_scan_blocks(int nb) {
    if (threadIdx.x == 0) {
        int run = 0;
        for (int b = 0; b < nb; b++) {
            int v = g_blocksums[b];
            g_blocksums[b] = run;
            run += v;
        }
    }
}

__global__ void k_scan_add(int N, int E) {
    int i = blockIdx.x * 1024 + threadIdx.x;
    if (i < N) {
        int v = g_off[i] + g_blocksums[blockIdx.x];
        g_off[i] = v;
        g_cursor[i] = v;
    }
    if (i == 0) g_off[N] = E;
}

// CSR fill: only the source index per edge (norm folded into y).
__global__ void k_fill_csr(int E) {
    int e = blockIdx.x * blockDim.x + threadIdx.x;
    if (e < E) {
        int s = g_idx[e];
        int d = g_idx[E + e];
        int pos = atomicAdd(&g_cursor[d], 1);
        g_src[pos] = s;
    }
}

// acc = E0 ; y0 = dinv (.) E0   (float4 elementwise)
__global__ void k_init(const float4* __restrict__ E0, int NQ) {
    int i = blockIdx.x * blockDim.x + threadIdx.x;
    if (i < NQ) {
        float4 v = E0[i];
        g_acc[i] = v;
        float di = g_dinv[i >> 4];
        float4 y; y.x = v.x * di; y.y = v.y * di; y.z = v.z * di; y.w = v.w * di;
        g_yA[i] = y;
    }
}

// 16 lanes per node (float4 each), 16 nodes per 256-thread block.
// Inner loop: pure gather-sum of y rows (256B coalesced per node per edge).
__global__ void k_propagate(const float4* __restrict__ y, float4* __restrict__ yn, int N) {
    int node = blockIdx.x * 16 + threadIdx.y;
    if (node >= N) return;
    int t = threadIdx.x;  // 0..15
    int beg = g_off[node];
    int end = g_off[node + 1];
    float4 s0 = make_float4(0.f, 0.f, 0.f, 0.f);
    float4 s1 = make_float4(0.f, 0.f, 0.f, 0.f);
    int e = beg;
    for (; e + 1 < end; e += 2) {
        int sa = g_src[e];
        int sb = g_src[e + 1];
        float4 va = y[sa * DQ + t];
        float4 vb = y[sb * DQ + t];
        s0.x += va.x; s0.y += va.y; s0.z += va.z; s0.w += va.w;
        s1.x += vb.x; s1.y += vb.y; s1.z += vb.z; s1.w += vb.w;
    }
    if (e < end) {
        float4 va = y[g_src[e] * DQ + t];
        s0.x += va.x; s0.y += va.y; s0.z += va.z; s0.w += va.w;
    }
    float di = g_dinv[node];
    float sx = di * (s0.x + s1.x);
    float sy = di * (s0.y + s1.y);
    float sz = di * (s0.z + s1.z);
    float sw = di * (s0.w + s1.w);
    int o = node * DQ + t;
    float4 a = g_acc[o];
    a.x += sx; a.y += sy; a.z += sz; a.w += sw;
    g_acc[o] = a;
    float4 yv; yv.x = di * sx; yv.y = di * sy; yv.z = di * sz; yv.w = di * sw;
    yn[o] = yv;
}

__global__ void k_final(const float4* __restrict__ E0, float4* __restrict__ out, int NQ) {
    int i = blockIdx.x * blockDim.x + threadIdx.x;
    if (i < NQ) {
        out[i] = E0[i];
        float4 a = g_acc[i];
        float4 r; r.x = a.x * 0.25f; r.y = a.y * 0.25f; r.z = a.z * 0.25f; r.w = a.w * 0.25f;
        out[NQ + i] = r;
    }
}

// ---------------------------------------------------------------------------

extern "C" void kernel_launch(void* const* d_in, const int* in_sizes, int n_in,
                              void* d_out, int out_size) {
    const float4* E0 = (const float4*)d_in[0];
    const void*   ei = d_in[1];
    float4*       out = (float4*)d_out;

    int N  = in_sizes[0] / D;   // 100000
    int E  = in_sizes[1] / 2;   // 1000000
    int NQ = N * DQ;            // N*D/4 float4 elements

    void *pA = nullptr, *pB = nullptr;
    cudaGetSymbolAddress(&pA, g_yA);
    cudaGetSymbolAddress(&pB, g_yB);
    float4* yA = (float4*)pA;
    float4* yB = (float4*)pB;

    const int T = 256;
    int nb_scan = (N + 1023) / 1024;
    int E2 = 2 * E;

    k_detect<<<1, 32>>>((const int*)ei);
    k_zero_deg<<<(N + T - 1) / T, T>>>(N);
    k_extract_hist<<<(E2 + T - 1) / T, T>>>(ei, E);

    k_scan_local<<<nb_scan, 1024>>>(N);
    k_scan_blocks<<<1, 32>>>(nb_scan);
    k_scan_add<<<nb_scan, 1024>>>(N, E);

    k_fill_csr<<<(E + T - 1) / T, T>>>(E);

    k_init<<<(NQ + T - 1) / T, T>>>(E0, NQ);

    dim3 pb(16, 16);
    int  pg = (N + 15) / 16;
    k_propagate<<<pg, pb>>>(yA, yB, N);
    k_propagate<<<pg, pb>>>(yB, yA, N);
    k_propagate<<<pg, pb>>>(yA, yB, N);

    k_final<<<(NQ + T - 1) / T, T>>>(E0, out, NQ);
}

// round 4
// speedup vs baseline: 2.3859x; 1.3280x over previous
#include <cuda_runtime.h>
#include <cuda_bf16.h>
#include <cuda_fp16.h>
#include <stdint.h>

// ---------------------------------------------------------------------------
// LightGCN: N=100000, D=64, E=1000000, 3 layers.
// out[0:ND] = E0 ; out[ND:2ND] = (E0 + x1 + x2 + x3)/4
//
// y = dinv (.) x stored in fp16 (accumulation fp32):
//   s        = sum_{src->dst} y[src]          (pure fp16 gather-sum)
//   x_l[dst] = dinv[dst] * s   (-> acc, fp32)
//   y_l[dst] = dinv[dst]^2 * s (-> fp16)
// Layer 3 is fused with the output finalize.
// ---------------------------------------------------------------------------

#define MAXN 100000
#define MAXE 1000000
#define D    64

__device__ int    g_is64;
__device__ int    g_idx[2 * MAXE];
__device__ int    g_deg[MAXN];
__device__ float  g_dinv[MAXN];
__device__ int    g_off[MAXN + 1];
__device__ int    g_cursor[MAXN];
__device__ int    g_blocksums[128];
__device__ int    g_src[MAXE];
__device__ uint4  g_yA[MAXN * 8];        // fp16 rows: 64 halfs = 8 uint4
__device__ uint4  g_yB[MAXN * 8];
__device__ float4 g_acc[MAXN * 16];

// ---------------------------------------------------------------------------
// Zero deg; block 0 / thread 0 also detects dtype: int64 values < 2^31 have
// every odd 32-bit word == 0 (impossible for 128 random int32 indices).
__global__ void k_detect_zero(const int* __restrict__ p, int N) {
    int i = blockIdx.x * blockDim.x + threadIdx.x;
    if (i < N) g_deg[i] = 0;
    if (i == 0) {
        int nz = 0;
        for (int j = 1; j < 256; j += 2) nz += (p[j] != 0);
        g_is64 = (nz == 0) ? 1 : 0;
    }
}

// Normalize indices to int32 AND histogram destinations in the same pass.
__global__ void k_extract_hist(const void* __restrict__ ei, int E) {
    int i = blockIdx.x * blockDim.x + threadIdx.x;
    int E2 = 2 * E;
    if (i < E2) {
        int v;
        if (g_is64) v = (int)((const long long*)ei)[i];
        else        v = ((const int*)ei)[i];
        g_idx[i] = v;
        if (i >= E) atomicAdd(&g_deg[v], 1);
    }
}

// Block-local exclusive scan of deg -> g_off (+ fused dinv computation).
__global__ void k_scan_local(int N) {
    __shared__ int sh[1024];
    int tid = threadIdx.x;
    int i = blockIdx.x * 1024 + tid;
    int v = (i < N) ? g_deg[i] : 0;
    if (i < N) g_dinv[i] = (v > 0) ? rsqrtf((float)v) : 0.0f;
    sh[tid] = v;
    __syncthreads();
    #pragma unroll
    for (int ofs = 1; ofs < 1024; ofs <<= 1) {
        int t = (tid >= ofs) ? sh[tid - ofs] : 0;
        __syncthreads();
        sh[tid] += t;
        __syncthreads();
    }
    if (i < N) g_off[i] = sh[tid] - v;
    if (tid == 1023) g_blocksums[blockIdx.x] = sh[1023];
}

// Parallel exclusive scan of the (<=128) block sums.
__global__ void k_scan_blocks(int nb) {
    __shared__ int sh[128];
    int tid = threadIdx.x;
    int v = (tid < nb) ? g_blocksums[tid] : 0;
    sh[tid] = v;
    __syncthreads();
    #pragma unroll
    for (int ofs = 1; ofs < 128; ofs <<= 1) {
        int t = (tid >= ofs) ? sh[tid - ofs] : 0;
        __syncthreads();
        sh[tid] += t;
        __syncthreads();
    }
    if (tid < nb) g_blocksums[tid] = sh[tid] - v;  // exclusive
}

__global__ void k_scan_add(int N, int E) {
    int i = blockIdx.x * 1024 + threadIdx.x;
    if (i < N) {
        int v = g_off[i] + g_blocksums[blockIdx.x];
        g_off[i] = v;
        g_cursor[i] = v;
    }
    if (i == 0) g_off[N] = E;
}

__global__ void k_fill_csr(int E) {
    int e = blockIdx.x * blockDim.x + threadIdx.x;
    if (e < E) {
        int s = g_idx[e];
        int d = g_idx[E + e];
        int pos = atomicAdd(&g_cursor[d], 1);
        g_src[pos] = s;
    }
}

// acc = E0 ; out[0:NQ] = E0 ; y0 = fp16(dinv (.) E0)
__global__ void k_init(const float4* __restrict__ E0, float4* __restrict__ out, int NQ) {
    int i = blockIdx.x * blockDim.x + threadIdx.x;
    if (i < NQ) {
        float4 v = E0[i];
        g_acc[i] = v;
        out[i] = v;
        float di = g_dinv[i >> 4];
        uint2 w;
        __half2* hw = (__half2*)&w;
        hw[0] = __floats2half2_rn(v.x * di, v.y * di);
        hw[1] = __floats2half2_rn(v.z * di, v.w * di);
        ((uint2*)g_yA)[i] = w;
    }
}

// 8 lanes per node (16B of fp16 each = 8 features), 32 nodes per 256-block.
__global__ void k_propagate(const uint4* __restrict__ y, uint4* __restrict__ yn, int N) {
    int node = blockIdx.x * 32 + threadIdx.y;
    if (node >= N) return;
    int t = threadIdx.x;  // 0..7
    int beg = g_off[node];
    int end = g_off[node + 1];
    float s0[8] = {0, 0, 0, 0, 0, 0, 0, 0};
    float s1[8] = {0, 0, 0, 0, 0, 0, 0, 0};
    int e = beg;
    for (; e + 1 < end; e += 2) {
        int sa = g_src[e];
        int sb = g_src[e + 1];
        uint4 ua = y[sa * 8 + t];
        uint4 ub = y[sb * 8 + t];
        const __half2* ha = (const __half2*)&ua;
        const __half2* hb = (const __half2*)&ub;
        #pragma unroll
        for (int j = 0; j < 4; j++) {
            float2 fa = __half22float2(ha[j]);
            float2 fb = __half22float2(hb[j]);
            s0[2 * j] += fa.x; s0[2 * j + 1] += fa.y;
            s1[2 * j] += fb.x; s1[2 * j + 1] += fb.y;
        }
    }
    if (e < end) {
        uint4 ua = y[g_src[e] * 8 + t];
        const __half2* ha = (const __half2*)&ua;
        #pragma unroll
        for (int j = 0; j < 4; j++) {
            float2 fa = __half22float2(ha[j]);
            s0[2 * j] += fa.x; s0[2 * j + 1] += fa.y;
        }
    }
    float di = g_dinv[node];
    float v[8];
    #pragma unroll
    for (int j = 0; j < 8; j++) v[j] = di * (s0[j] + s1[j]);  // x-layer contribution
    int o4 = node * 16 + t * 2;
    float4 a0 = g_acc[o4], a1 = g_acc[o4 + 1];
    a0.x += v[0]; a0.y += v[1]; a0.z += v[2]; a0.w += v[3];
    a1.x += v[4]; a1.y += v[5]; a1.z += v[6]; a1.w += v[7];
    g_acc[o4] = a0; g_acc[o4 + 1] = a1;
    uint4 w;
    __half2* hw = (__half2*)&w;
    #pragma unroll
    for (int j = 0; j < 4; j++)
        hw[j] = __floats2half2_rn(di * v[2 * j], di * v[2 * j + 1]);
    yn[node * 8 + t] = w;
}

// Final layer fused with output: out[NQ + o] = 0.25 * (acc + di*s); no y/acc writes.
__global__ void k_propagate_last(const uint4* __restrict__ y, float4* __restrict__ out,
                                 int N, int NQ) {
    int node = blockIdx.x * 32 + threadIdx.y;
    if (node >= N) return;
    int t = threadIdx.x;
    int beg = g_off[node];
    int end = g_off[node + 1];
    float s0[8] = {0, 0, 0, 0, 0, 0, 0, 0};
    float s1[8] = {0, 0, 0, 0, 0, 0, 0, 0};
    int e = beg;
    for (; e + 1 < end; e += 2) {
        int sa = g_src[e];
        int sb = g_src[e + 1];
        uint4 ua = y[sa * 8 + t];
        uint4 ub = y[sb * 8 + t];
        const __half2* ha = (const __half2*)&ua;
        const __half2* hb = (const __half2*)&ub;
        #pragma unroll
        for (int j = 0; j < 4; j++) {
            float2 fa = __half22float2(ha[j]);
            float2 fb = __half22float2(hb[j]);
            s0[2 * j] += fa.x; s0[2 * j + 1] += fa.y;
            s1[2 * j] += fb.x; s1[2 * j + 1] += fb.y;
        }
    }
    if (e < end) {
        uint4 ua = y[g_src[e] * 8 + t];
        const __half2* ha = (const __half2*)&ua;
        #pragma unroll
        for (int j = 0; j < 4; j++) {
            float2 fa = __half22float2(ha[j]);
            s0[2 * j] += fa.x; s0[2 * j + 1] += fa.y;
        }
    }
    float di = g_dinv[node];
    int o4 = node * 16 + t * 2;
    float4 a0 = g_acc[o4], a1 = g_acc[o4 + 1];
    float4 r0, r1;
    r0.x = 0.25f * (a0.x + di * (s0[0] + s1[0]));
    r0.y = 0.25f * (a0.y + di * (s0[1] + s1[1]));
    r0.z = 0.25f * (a0.z + di * (s0[2] + s1[2]));
    r0.w = 0.25f * (a0.w + di * (s0[3] + s1[3]));
    r1.x = 0.25f * (a1.x + di * (s0[4] + s1[4]));
    r1.y = 0.25f * (a1.y + di * (s0[5] + s1[5]));
    r1.z = 0.25f * (a1.z + di * (s0[6] + s1[6]));
    r1.w = 0.25f * (a1.w + di * (s0[7] + s1[7]));
    out[NQ + o4] = r0;
    out[NQ + o4 + 1] = r1;
}

// ---------------------------------------------------------------------------

extern "C" void kernel_launch(void* const* d_in, const int* in_sizes, int n_in,
                              void* d_out, int out_size) {
    const float4* E0 = (const float4*)d_in[0];
    const void*   ei = d_in[1];
    float4*       out = (float4*)d_out;

    int N  = in_sizes[0] / D;   // 100000
    int E  = in_sizes[1] / 2;   // 1000000
    int NQ = N * 16;            // float4 count per half of out

    void *pA = nullptr, *pB = nullptr;
    cudaGetSymbolAddress(&pA, g_yA);
    cudaGetSymbolAddress(&pB, g_yB);
    uint4* yA = (uint4*)pA;
    uint4* yB = (uint4*)pB;

    const int T = 256;
    int nb_scan = (N + 1023) / 1024;
    int E2 = 2 * E;

    k_detect_zero<<<(N + T - 1) / T, T>>>((const int*)ei, N);
    k_extract_hist<<<(E2 + T - 1) / T, T>>>(ei, E);

    k_scan_local<<<nb_scan, 1024>>>(N);
    k_scan_blocks<<<1, 128>>>(nb_scan);
    k_scan_add<<<nb_scan, 1024>>>(N, E);

    k_fill_csr<<<(E + T - 1) / T, T>>>(E);

    k_init<<<(NQ + T - 1) / T, T>>>(E0, out, NQ);

    dim3 pb(8, 32);
    int  pg = (N + 31) / 32;
    k_propagate<<<pg, pb>>>(yA, yB, N);
    k_propagate<<<pg, pb>>>(yB, yA, N);
    k_propagate_last<<<pg, pb>>>(yA, out, N, NQ);
}

// round 5
// speedup vs baseline: 2.4860x; 1.0419x over previous
#include <cuda_runtime.h>
#include <cuda_fp16.h>
#include <stdint.h>

// ---------------------------------------------------------------------------
// LightGCN: N=100000, D=64, E=1000000, 3 layers.
// out[0:ND] = E0 ; out[ND:2ND] = (E0 + x1 + x2 + x3)/4
//
// y = dinv (.) x stored fp16; x_l = di*s_l, y_l = di^2*s_l, s_l = sum y_{l-1}[src].
// No fp32 accumulator: final kernel reconstructs x1 = y1*sqrt(deg), x2 = y2*sqrt(deg).
// g_deg is zero at module load and re-zeroed by k_init each call (graph-replay safe).
// ---------------------------------------------------------------------------

#define MAXN 100000
#define MAXE 1000000
#define D    64

__device__ int    g_deg[MAXN];        // zero-init at load; re-zeroed by k_init
__device__ float  g_dinv[MAXN];       // deg^-1/2 (0 if deg==0)
__device__ float  g_rdi[MAXN];        // deg^+1/2 (0 if deg==0)
__device__ int    g_off[MAXN + 1];
__device__ int    g_cursor[MAXN];
__device__ int    g_blocksums[128];
__device__ int    g_src[MAXE];
__device__ uint4  g_y0[MAXN * 8];     // fp16 rows: 64 halfs = 8 uint4
__device__ uint4  g_y1[MAXN * 8];
__device__ uint4  g_y2[MAXN * 8];

// ---------------------------------------------------------------------------
// Per-block dtype sniff: int64 indices < 2^31 have every odd 32-bit word == 0.
// 128 random int32 indices all being zero is impossible (p ~ 1e-640).
__device__ __forceinline__ bool block_is64(const int* __restrict__ p, int* s_flag) {
    if (threadIdx.x == 0) {
        int nz = 0;
        #pragma unroll 8
        for (int j = 1; j < 256; j += 2) nz += (p[j] != 0);
        *s_flag = (nz == 0);
    }
    __syncthreads();
    return *s_flag != 0;
}

__global__ void k_hist(const void* __restrict__ ei, int E) {
    __shared__ int s64;
    bool is64 = block_is64((const int*)ei, &s64);
    int e = blockIdx.x * blockDim.x + threadIdx.x;
    if (e < E) {
        int d = is64 ? (int)((const long long*)ei)[E + e]
                     : ((const int*)ei)[E + e];
        atomicAdd(&g_deg[d], 1);
    }
}

// Block-local exclusive scan of deg -> g_off; also dinv/rdi; block totals out.
__global__ void k_scan_local(int N) {
    __shared__ int sh[1024];
    int tid = threadIdx.x;
    int i = blockIdx.x * 1024 + tid;
    int v = (i < N) ? g_deg[i] : 0;
    if (i < N) {
        float fv = (float)v;
        g_dinv[i] = (v > 0) ? rsqrtf(fv) : 0.0f;
        g_rdi[i]  = (v > 0) ? sqrtf(fv)  : 0.0f;
    }
    sh[tid] = v;
    __syncthreads();
    #pragma unroll
    for (int ofs = 1; ofs < 1024; ofs <<= 1) {
        int t = (tid >= ofs) ? sh[tid - ofs] : 0;
        __syncthreads();
        sh[tid] += t;
        __syncthreads();
    }
    if (i < N) g_off[i] = sh[tid] - v;
    if (tid == 1023) g_blocksums[blockIdx.x] = sh[1023];
}

// Add inter-block base (reduced inline from g_blocksums) -> final off + cursor.
__global__ void k_scan_add(int N, int E, int nb) {
    __shared__ int red[128];
    int tid = threadIdx.x;
    if (tid < 128) red[tid] = (tid < nb && tid < blockIdx.x) ? g_blocksums[tid] : 0;
    __syncthreads();
    #pragma unroll
    for (int ofs = 64; ofs > 0; ofs >>= 1) {
        if (tid < ofs) red[tid] += red[tid + ofs];
        __syncthreads();
    }
    int base = red[0];
    int i = blockIdx.x * 1024 + tid;
    if (i < N) {
        int v = g_off[i] + base;
        g_off[i] = v;
        g_cursor[i] = v;
    }
    if (i == 0) g_off[N] = E;
}

__global__ void k_fill(const void* __restrict__ ei, int E) {
    __shared__ int s64;
    bool is64 = block_is64((const int*)ei, &s64);
    int e = blockIdx.x * blockDim.x + threadIdx.x;
    if (e < E) {
        int s, d;
        if (is64) {
            s = (int)((const long long*)ei)[e];
            d = (int)((const long long*)ei)[E + e];
        } else {
            s = ((const int*)ei)[e];
            d = ((const int*)ei)[E + e];
        }
        int pos = atomicAdd(&g_cursor[d], 1);
        g_src[pos] = s;
    }
}

// out[0:NQ] = E0 ; y0 = fp16(dinv (.) E0) ; re-zero deg for next graph replay.
__global__ void k_init(const float4* __restrict__ E0, float4* __restrict__ out,
                       int NQ, int N) {
    int i = blockIdx.x * blockDim.x + threadIdx.x;
    if (i < N) g_deg[i] = 0;   // deg dead after scan; reset for next call
    if (i < NQ) {
        float4 v = E0[i];
        out[i] = v;
        float di = g_dinv[i >> 4];
        uint2 w;
        __half2* hw = (__half2*)&w;
        hw[0] = __floats2half2_rn(v.x * di, v.y * di);
        hw[1] = __floats2half2_rn(v.z * di, v.w * di);
        ((uint2*)g_y0)[i] = w;
    }
}

// 8 lanes/node (16B fp16 each), 32 nodes per 256-block. Pure gather-sum.
__global__ void k_propagate(const uint4* __restrict__ y, uint4* __restrict__ yn, int N) {
    int node = blockIdx.x * 32 + threadIdx.y;
    if (node >= N) return;
    int t = threadIdx.x;  // 0..7
    int beg = g_off[node];
    int end = g_off[node + 1];
    float s0[8] = {0, 0, 0, 0, 0, 0, 0, 0};
    float s1[8] = {0, 0, 0, 0, 0, 0, 0, 0};
    int e = beg;
    for (; e + 1 < end; e += 2) {
        int sa = g_src[e];
        int sb = g_src[e + 1];
        uint4 ua = y[sa * 8 + t];
        uint4 ub = y[sb * 8 + t];
        const __half2* ha = (const __half2*)&ua;
        const __half2* hb = (const __half2*)&ub;
        #pragma unroll
        for (int j = 0; j < 4; j++) {
            float2 fa = __half22float2(ha[j]);
            float2 fb = __half22float2(hb[j]);
            s0[2 * j] += fa.x; s0[2 * j + 1] += fa.y;
            s1[2 * j] += fb.x; s1[2 * j + 1] += fb.y;
        }
    }
    if (e < end) {
        uint4 ua = y[g_src[e] * 8 + t];
        const __half2* ha = (const __half2*)&ua;
        #pragma unroll
        for (int j = 0; j < 4; j++) {
            float2 fa = __half22float2(ha[j]);
            s0[2 * j] += fa.x; s0[2 * j + 1] += fa.y;
        }
    }
    float di2 = g_dinv[node];
    di2 *= di2;
    uint4 w;
    __half2* hw = (__half2*)&w;
    #pragma unroll
    for (int j = 0; j < 4; j++)
        hw[j] = __floats2half2_rn(di2 * (s0[2 * j] + s1[2 * j]),
                                  di2 * (s0[2 * j + 1] + s1[2 * j + 1]));
    yn[node * 8 + t] = w;
}

// Final layer fused with output:
// out[NQ+o] = 0.25*(E0 + y1*rdi + y2*rdi + di*s3), s3 gathered from y2.
__global__ void k_propagate_last(const uint4* __restrict__ y2,
                                 const uint4* __restrict__ y1,
                                 const float4* __restrict__ E0,
                                 float4* __restrict__ out, int N, int NQ) {
    int node = blockIdx.x * 32 + threadIdx.y;
    if (node >= N) return;
    int t = threadIdx.x;
    int beg = g_off[node];
    int end = g_off[node + 1];
    float s0[8] = {0, 0, 0, 0, 0, 0, 0, 0};
    float s1[8] = {0, 0, 0, 0, 0, 0, 0, 0};
    int e = beg;
    for (; e + 1 < end; e += 2) {
        int sa = g_src[e];
        int sb = g_src[e + 1];
        uint4 ua = y2[sa * 8 + t];
        uint4 ub = y2[sb * 8 + t];
        const __half2* ha = (const __half2*)&ua;
        const __half2* hb = (const __half2*)&ub;
        #pragma unroll
        for (int j = 0; j < 4; j++) {
            float2 fa = __half22float2(ha[j]);
            float2 fb = __half22float2(hb[j]);
            s0[2 * j] += fa.x; s0[2 * j + 1] += fa.y;
            s1[2 * j] += fb.x; s1[2 * j + 1] += fb.y;
        }
    }
    if (e < end) {
        uint4 ua = y2[g_src[e] * 8 + t];
        const __half2* ha = (const __half2*)&ua;
        #pragma unroll
        for (int j = 0; j < 4; j++) {
            float2 fa = __half22float2(ha[j]);
            s0[2 * j] += fa.x; s0[2 * j + 1] += fa.y;
        }
    }
    float di  = g_dinv[node];
    float rdi = g_rdi[node];

    // Own rows of y1, y2 -> x1, x2
    uint4 u1 = y1[node * 8 + t];
    uint4 u2 = y2[node * 8 + t];
    const __half2* h1 = (const __half2*)&u1;
    const __half2* h2 = (const __half2*)&u2;

    float r[8];
    #pragma unroll
    for (int j = 0; j < 4; j++) {
        float2 f1 = __half22float2(h1[j]);
        float2 f2 = __half22float2(h2[j]);
        r[2 * j]     = rdi * (f1.x + f2.x) + di * (s0[2 * j]     + s1[2 * j]);
        r[2 * j + 1] = rdi * (f1.y + f2.y) + di * (s0[2 * j + 1] + s1[2 * j + 1]);
    }

    int o4 = node * 16 + t * 2;
    float4 e0a = E0[o4], e0b = E0[o4 + 1];
    float4 r0, r1;
    r0.x = 0.25f * (e0a.x + r[0]);
    r0.y = 0.25f * (e0a.y + r[1]);
    r0.z = 0.25f * (e0a.z + r[2]);
    r0.w = 0.25f * (e0a.w + r[3]);
    r1.x = 0.25f * (e0b.x + r[4]);
    r1.y = 0.25f * (e0b.y + r[5]);
    r1.z = 0.25f * (e0b.z + r[6]);
    r1.w = 0.25f * (e0b.w + r[7]);
    out[NQ + o4] = r0;
    out[NQ + o4 + 1] = r1;
}

// ---------------------------------------------------------------------------

extern "C" void kernel_launch(void* const* d_in, const int* in_sizes, int n_in,
                              void* d_out, int out_size) {
    const float4* E0 = (const float4*)d_in[0];
    const void*   ei = d_in[1];
    float4*       out = (float4*)d_out;

    int N  = in_sizes[0] / D;   // 100000
    int E  = in_sizes[1] / 2;   // 1000000
    int NQ = N * 16;

    void *p0 = nullptr, *p1 = nullptr, *p2 = nullptr;
    cudaGetSymbolAddress(&p0, g_y0);
    cudaGetSymbolAddress(&p1, g_y1);
    cudaGetSymbolAddress(&p2, g_y2);
    uint4* y0 = (uint4*)p0;
    uint4* y1 = (uint4*)p1;
    uint4* y2 = (uint4*)p2;

    const int T = 256;
    int nb_scan = (N + 1023) / 1024;

    k_hist<<<(E + T - 1) / T, T>>>(ei, E);
    k_scan_local<<<nb_scan, 1024>>>(N);
    k_scan_add<<<nb_scan, 1024>>>(N, E, nb_scan);
    k_fill<<<(E + T - 1) / T, T>>>(ei, E);
    k_init<<<(NQ + T - 1) / T, T>>>(E0, out, NQ, N);

    dim3 pb(8, 32);
    int  pg = (N + 31) / 32;
    k_propagate<<<pg, pb>>>(y0, y1, N);
    k_propagate<<<pg, pb>>>(y1, y2, N);
    k_propagate_last<<<pg, pb>>>(y2, y1, E0, out, N, NQ);
}

// round 6
// speedup vs baseline: 2.5716x; 1.0344x over previous
#include <cuda_runtime.h>
#include <cuda_fp16.h>
#include <stdint.h>

// ---------------------------------------------------------------------------
// LightGCN: N=100000, D=64, E=1000000, 3 layers.
// out[0:ND] = E0 ; out[ND:2ND] = (E0 + x1 + x2 + x3)/4
//
// y = dinv (.) x stored fp16; x_l = di*s_l, y_l = di^2*s_l, s_l = sum y_{l-1}[src].
// Final kernel reconstructs x1,x2 from y1,y2 via rdi = sqrt(deg).
// 6 launches: hist, scan(single-pass), fill+init(fused), prop, prop, prop_last.
// ---------------------------------------------------------------------------

#define MAXN 100000
#define MAXE 1000000
#define D    64

__device__ int    g_deg[MAXN];        // zero at load; re-zeroed in fill_init
__device__ float  g_dinv[MAXN];
__device__ float  g_rdi[MAXN];
__device__ int    g_off[MAXN + 1];
__device__ int    g_cursor[MAXN];
__device__ int    g_blocksums[128];
__device__ int    g_scanflag[128];    // zero at load; re-zeroed in k_hist
__device__ int    g_src[MAXE];
__device__ uint4  g_y0[MAXN * 8];
__device__ uint4  g_y1[MAXN * 8];
__device__ uint4  g_y2[MAXN * 8];

// ---------------------------------------------------------------------------
// Per-block dtype sniff: int64 indices < 2^31 have every odd 32-bit word == 0.
__device__ __forceinline__ bool block_is64(const int* __restrict__ p, int* s_flag) {
    if (threadIdx.x == 0) {
        int nz = 0;
        #pragma unroll 8
        for (int j = 1; j < 256; j += 2) nz += (p[j] != 0);
        *s_flag = (nz == 0);
    }
    __syncthreads();
    return *s_flag != 0;
}

// Histogram of destinations, 4 edges per thread. Block 0 also resets scan flags.
__global__ void k_hist(const void* __restrict__ ei, int E) {
    __shared__ int s64;
    bool is64 = block_is64((const int*)ei, &s64);
    if (blockIdx.x == 0 && threadIdx.x < 128) g_scanflag[threadIdx.x] = 0;
    int base = (blockIdx.x * blockDim.x + threadIdx.x) * 4;
    if (base >= E) return;
    int d0, d1, d2, d3;
    int n = E - base; // >=1
    if (is64) {
        const long long* p = (const long long*)ei + E + base;
        if (n >= 4) {
            longlong2 a = ((const longlong2*)p)[0];
            longlong2 b = ((const longlong2*)p)[1];
            d0 = (int)a.x; d1 = (int)a.y; d2 = (int)b.x; d3 = (int)b.y;
        } else {
            d0 = (int)p[0];
            d1 = (n > 1) ? (int)p[1] : -1;
            d2 = (n > 2) ? (int)p[2] : -1;
            d3 = -1;
        }
    } else {
        const int* p = (const int*)ei + E + base;
        if (n >= 4) {
            int4 a = *(const int4*)p;
            d0 = a.x; d1 = a.y; d2 = a.z; d3 = a.w;
        } else {
            d0 = p[0];
            d1 = (n > 1) ? p[1] : -1;
            d2 = (n > 2) ? p[2] : -1;
            d3 = -1;
        }
    }
    atomicAdd(&g_deg[d0], 1);
    if (d1 >= 0) atomicAdd(&g_deg[d1], 1);
    if (d2 >= 0) atomicAdd(&g_deg[d2], 1);
    if (d3 >= 0) atomicAdd(&g_deg[d3], 1);
}

// Single-pass exclusive scan of deg -> off (+ dinv/rdi). 98 blocks x 1024:
// every block is resident simultaneously, so cross-block polling is safe.
__global__ void k_scan(int N, int E) {
    __shared__ int sh[1024];
    int tid = threadIdx.x;
    int bid = blockIdx.x;
    int i = bid * 1024 + tid;
    int v = (i < N) ? g_deg[i] : 0;
    if (i < N) {
        float fv = (float)v;
        g_dinv[i] = (v > 0) ? rsqrtf(fv) : 0.0f;
        g_rdi[i]  = (v > 0) ? sqrtf(fv)  : 0.0f;
    }
    sh[tid] = v;
    __syncthreads();
    #pragma unroll
    for (int ofs = 1; ofs < 1024; ofs <<= 1) {
        int t = (tid >= ofs) ? sh[tid - ofs] : 0;
        __syncthreads();
        sh[tid] += t;
        __syncthreads();
    }
    int incl = sh[tid];
    // Publish aggregate with release semantics.
    if (tid == 1023) {
        g_blocksums[bid] = incl;
        __threadfence();
        ((volatile int*)g_scanflag)[bid] = 1;
    }
    __syncthreads();
    // Poll all predecessors' aggregates in parallel, then tree-reduce.
    int part = 0;
    if (tid < bid) {
        while (((volatile int*)g_scanflag)[tid] == 0) {}
        __threadfence();
        part = g_blocksums[tid];
    }
    sh[tid] = part;
    __syncthreads();
    #pragma unroll
    for (int ofs = 512; ofs > 0; ofs >>= 1) {
        if (tid < ofs) sh[tid] += sh[tid + ofs];
        __syncthreads();
    }
    int base = sh[0];
    if (i < N) {
        int o = base + incl - v;
        g_off[i] = o;
        g_cursor[i] = o;
    }
    if (i == 0) g_off[N] = E;
}

// Fused: CSR fill (i<E, atomic-latency bound) + init (i<NQ, bandwidth bound)
// + deg re-zero (i<N, for graph replay).
__global__ void k_fill_init(const void* __restrict__ ei,
                            const float4* __restrict__ E0,
                            float4* __restrict__ out,
                            int E, int NQ, int N) {
    __shared__ int s64;
    bool is64 = block_is64((const int*)ei, &s64);
    int i = blockIdx.x * blockDim.x + threadIdx.x;
    if (i < N) g_deg[i] = 0;
    if (i < E) {
        int s, d;
        if (is64) {
            s = (int)((const long long*)ei)[i];
            d = (int)((const long long*)ei)[E + i];
        } else {
            s = ((const int*)ei)[i];
            d = ((const int*)ei)[E + i];
        }
        int pos = atomicAdd(&g_cursor[d], 1);
        g_src[pos] = s;
    }
    if (i < NQ) {
        float4 v = E0[i];
        out[i] = v;
        float di = g_dinv[i >> 4];
        uint2 w;
        __half2* hw = (__half2*)&w;
        hw[0] = __floats2half2_rn(v.x * di, v.y * di);
        hw[1] = __floats2half2_rn(v.z * di, v.w * di);
        ((uint2*)g_y0)[i] = w;
    }
}

// 8 lanes/node (16B fp16 each), 32 nodes per 256-block. Pure gather-sum.
__global__ void k_propagate(const uint4* __restrict__ y, uint4* __restrict__ yn, int N) {
    int node = blockIdx.x * 32 + threadIdx.y;
    if (node >= N) return;
    int t = threadIdx.x;  // 0..7
    int beg = g_off[node];
    int end = g_off[node + 1];
    float s0[8] = {0, 0, 0, 0, 0, 0, 0, 0};
    float s1[8] = {0, 0, 0, 0, 0, 0, 0, 0};
    int e = beg;
    for (; e + 1 < end; e += 2) {
        int sa = g_src[e];
        int sb = g_src[e + 1];
        uint4 ua = y[sa * 8 + t];
        uint4 ub = y[sb * 8 + t];
        const __half2* ha = (const __half2*)&ua;
        const __half2* hb = (const __half2*)&ub;
        #pragma unroll
        for (int j = 0; j < 4; j++) {
            float2 fa = __half22float2(ha[j]);
            float2 fb = __half22float2(hb[j]);
            s0[2 * j] += fa.x; s0[2 * j + 1] += fa.y;
            s1[2 * j] += fb.x; s1[2 * j + 1] += fb.y;
        }
    }
    if (e < end) {
        uint4 ua = y[g_src[e] * 8 + t];
        const __half2* ha = (const __half2*)&ua;
        #pragma unroll
        for (int j = 0; j < 4; j++) {
            float2 fa = __half22float2(ha[j]);
            s0[2 * j] += fa.x; s0[2 * j + 1] += fa.y;
        }
    }
    float di2 = g_dinv[node];
    di2 *= di2;
    uint4 w;
    __half2* hw = (__half2*)&w;
    #pragma unroll
    for (int j = 0; j < 4; j++)
        hw[j] = __floats2half2_rn(di2 * (s0[2 * j] + s1[2 * j]),
                                  di2 * (s0[2 * j + 1] + s1[2 * j + 1]));
    yn[node * 8 + t] = w;
}

// Final layer fused with output: out = 0.25*(E0 + (y1+y2)*rdi + di*s3).
__global__ void k_propagate_last(const uint4* __restrict__ y2,
                                 const uint4* __restrict__ y1,
                                 const float4* __restrict__ E0,
                                 float4* __restrict__ out, int N, int NQ) {
    int node = blockIdx.x * 32 + threadIdx.y;
    if (node >= N) return;
    int t = threadIdx.x;
    int beg = g_off[node];
    int end = g_off[node + 1];
    float s0[8] = {0, 0, 0, 0, 0, 0, 0, 0};
    float s1[8] = {0, 0, 0, 0, 0, 0, 0, 0};
    int e = beg;
    for (; e + 1 < end; e += 2) {
        int sa = g_src[e];
        int sb = g_src[e + 1];
        uint4 ua = y2[sa * 8 + t];
        uint4 ub = y2[sb * 8 + t];
        const __half2* ha = (const __half2*)&ua;
        const __half2* hb = (const __half2*)&ub;
        #pragma unroll
        for (int j = 0; j < 4; j++) {
            float2 fa = __half22float2(ha[j]);
            float2 fb = __half22float2(hb[j]);
            s0[2 * j] += fa.x; s0[2 * j + 1] += fa.y;
            s1[2 * j] += fb.x; s1[2 * j + 1] += fb.y;
        }
    }
    if (e < end) {
        uint4 ua = y2[g_src[e] * 8 + t];
        const __half2* ha = (const __half2*)&ua;
        #pragma unroll
        for (int j = 0; j < 4; j++) {
            float2 fa = __half22float2(ha[j]);
            s0[2 * j] += fa.x; s0[2 * j + 1] += fa.y;
        }
    }
    float di  = g_dinv[node];
    float rdi = g_rdi[node];

    uint4 u1 = y1[node * 8 + t];
    uint4 u2 = y2[node * 8 + t];
    const __half2* h1 = (const __half2*)&u1;
    const __half2* h2 = (const __half2*)&u2;

    float r[8];
    #pragma unroll
    for (int j = 0; j < 4; j++) {
        float2 f1 = __half22float2(h1[j]);
        float2 f2 = __half22float2(h2[j]);
        r[2 * j]     = rdi * (f1.x + f2.x) + di * (s0[2 * j]     + s1[2 * j]);
        r[2 * j + 1] = rdi * (f1.y + f2.y) + di * (s0[2 * j + 1] + s1[2 * j + 1]);
    }

    int o4 = node * 16 + t * 2;
    float4 e0a = E0[o4], e0b = E0[o4 + 1];
    float4 r0, r1;
    r0.x = 0.25f * (e0a.x + r[0]);
    r0.y = 0.25f * (e0a.y + r[1]);
    r0.z = 0.25f * (e0a.z + r[2]);
    r0.w = 0.25f * (e0a.w + r[3]);
    r1.x = 0.25f * (e0b.x + r[4]);
    r1.y = 0.25f * (e0b.y + r[5]);
    r1.z = 0.25f * (e0b.z + r[6]);
    r1.w = 0.25f * (e0b.w + r[7]);
    out[NQ + o4] = r0;
    out[NQ + o4 + 1] = r1;
}

// ---------------------------------------------------------------------------

extern "C" void kernel_launch(void* const* d_in, const int* in_sizes, int n_in,
                              void* d_out, int out_size) {
    const float4* E0 = (const float4*)d_in[0];
    const void*   ei = d_in[1];
    float4*       out = (float4*)d_out;

    int N  = in_sizes[0] / D;   // 100000
    int E  = in_sizes[1] / 2;   // 1000000
    int NQ = N * 16;

    void *p0 = nullptr, *p1 = nullptr, *p2 = nullptr;
    cudaGetSymbolAddress(&p0, g_y0);
    cudaGetSymbolAddress(&p1, g_y1);
    cudaGetSymbolAddress(&p2, g_y2);
    uint4* y0 = (uint4*)p0;
    uint4* y1 = (uint4*)p1;
    uint4* y2 = (uint4*)p2;

    const int T = 256;
    int nb_scan = (N + 1023) / 1024;   // 98 blocks, all resident
    int nb_hist = ((E + 3) / 4 + T - 1) / T;

    k_hist<<<nb_hist, T>>>(ei, E);
    k_scan<<<nb_scan, 1024>>>(N, E);
    k_fill_init<<<(NQ + T - 1) / T, T>>>(ei, E0, out, E, NQ, N);

    dim3 pb(8, 32);
    int  pg = (N + 31) / 32;
    k_propagate<<<pg, pb>>>(y0, y1, N);
    k_propagate<<<pg, pb>>>(y1, y2, N);
    k_propagate_last<<<pg, pb>>>(y2, y1, E0, out, N, NQ);
}